// round 13
// baseline (speedup 1.0000x reference)
#include <cuda_runtime.h>
#include <math.h>
#include <stdint.h>

#define Bsz  64
#define Tlen 2048
#define Hd   128
#define G4   512
#define Cout 7

#define WS_STRIDE 264     // Wsm [k][n_compact], 128 x 264 u32
#define HC_STRIDE 132     // hchunk [t][k], 64 x 132 u32

// ---------------- device scratch ----------------
__device__ float g_v0[G4];
__device__ float g_u0[G4];
__device__ float g_G1[(size_t)Tlen * Bsz * G4];     // layer-1 input-gate preacts
__device__ float g_pool[Bsz * 3 * Hd];

__device__ __forceinline__ float sigf(float x)  { return 1.0f / (1.0f + __expf(-x)); }
__device__ __forceinline__ float tanhfast(float x) {
    return fmaf(-2.0f, 1.0f / (__expf(2.0f * x) + 1.0f), 1.0f);
}

// ---- packed f32x2 ----
__device__ __forceinline__ void fma2(unsigned long long& d, unsigned long long a, unsigned long long b) {
    asm("fma.rn.f32x2 %0, %1, %2, %0;" : "+l"(d) : "l"(a), "l"(b));
}
__device__ __forceinline__ float2 upk2(unsigned long long v) {
    float2 r; asm("mov.b64 {%0, %1}, %2;" : "=f"(r.x), "=f"(r.y) : "l"(v)); return r;
}

// ---- tf32 ----
__device__ __forceinline__ uint32_t f2tf(float f) {
    uint32_t r; asm("cvt.rna.tf32.f32 %0, %1;" : "=r"(r) : "f"(f)); return r;
}
__device__ __forceinline__ void mma_tf32(float* c, const uint32_t* a, const uint32_t* b) {
    asm("mma.sync.aligned.m16n8k8.row.col.f32.tf32.tf32.f32 "
        "{%0,%1,%2,%3}, {%4,%5,%6,%7}, {%8,%9}, {%0,%1,%2,%3};"
        : "+f"(c[0]), "+f"(c[1]), "+f"(c[2]), "+f"(c[3])
        : "r"(a[0]), "r"(a[1]), "r"(a[2]), "r"(a[3]), "r"(b[0]), "r"(b[1]));
}

__device__ __forceinline__ uint32_t smem_u32(const void* p) {
    uint32_t a;
    asm("{ .reg .u64 t; cvta.to.shared.u64 t, %1; cvt.u32.u64 %0, t; }" : "=r"(a) : "l"(p));
    return a;
}
__device__ __forceinline__ uint32_t mapa32(uint32_t a, uint32_t rank) {
    uint32_t d;
    asm("mapa.shared::cluster.u32 %0, %1, %2;" : "=r"(d) : "r"(a), "r"(rank));
    return d;
}
__device__ __forceinline__ void st_async_remote(uint32_t raddr, float v, uint32_t rmbar) {
    asm volatile("st.async.shared::cluster.mbarrier::complete_tx::bytes.b32 [%0], %1, [%2];"
                 :: "r"(raddr), "r"(__float_as_uint(v)), "r"(rmbar) : "memory");
}
__device__ __forceinline__ void mbar_init(uint32_t mbar, uint32_t cnt) {
    asm volatile("mbarrier.init.shared.b64 [%0], %1;" :: "r"(mbar), "r"(cnt) : "memory");
}
__device__ __forceinline__ void mbar_expect_tx(uint32_t mbar, uint32_t bytes) {
    asm volatile("mbarrier.arrive.expect_tx.shared.b64 _, [%0], %1;" :: "r"(mbar), "r"(bytes) : "memory");
}
__device__ __forceinline__ void mbar_wait(uint32_t mbar, uint32_t parity) {
    uint32_t done;
    asm volatile(
        "{\n\t.reg .pred p;\n\t"
        "mbarrier.try_wait.parity.acquire.cluster.shared::cta.b64 p, [%1], %2;\n\t"
        "selp.b32 %0, 1, 0, p;\n\t}"
        : "=r"(done) : "r"(mbar), "r"(parity) : "memory");
    if (!done) {
        asm volatile(
            "{\n\t.reg .pred P1;\n\t"
            "WL_%=:\n\t"
            "mbarrier.try_wait.parity.acquire.cluster.shared::cta.b64 P1, [%0], %1, 0x989680;\n\t"
            "@P1 bra.uni WD_%=;\n\t"
            "bra.uni WL_%=;\n\t"
            "WD_%=:\n\t}"
            :: "r"(mbar), "r"(parity) : "memory");
    }
}

// ---------------- prep ----------------
__global__ void prep_kernel(const float* __restrict__ Wih0, const float* __restrict__ ffw,
                            const float* __restrict__ ffb,  const float* __restrict__ b0) {
    int g = blockIdx.x * 64 + threadIdx.x;
    float v = 0.f, u = 0.f;
    #pragma unroll 8
    for (int k = 0; k < Hd; k++) {
        float w = Wih0[g * Hd + k];
        v = fmaf(w, ffw[k], v);
        u = fmaf(w, ffb[k], u);
    }
    g_v0[g] = v;
    g_u0[g] = u + b0[g];
}

// ---------------- chunk burst: G1[tbase..tbase+63][CTA's 256 gates] via TF32 mma ----
// A = hchunk [64 t][128 k] tf32, B = Wsm [128 k][256 n_compact] tf32.
// Fragment mapping identical to the R11-validated gemm.
__device__ __forceinline__ void burst_gemv(const uint32_t* __restrict__ hchunk,
                                           const uint32_t* __restrict__ Wsm,
                                           const float* __restrict__ bias_sm,
                                           int tbase, int b, int rank, int tid) {
    const int lane = tid & 31;
    const int lr = lane >> 2, lc = lane & 3;
    const int n_base = (tid >> 5) * 32;          // warp's compact-n range

    #pragma unroll
    for (int mp = 0; mp < 2; mp++) {             // 2 passes x 2 m-tiles = 64 t rows
        float acc[2][4][4];
        #pragma unroll
        for (int mt = 0; mt < 2; mt++)
            #pragma unroll
            for (int nt = 0; nt < 4; nt++)
                #pragma unroll
                for (int i = 0; i < 4; i++) acc[mt][nt][i] = 0.f;

        #pragma unroll
        for (int kt = 0; kt < 16; kt++) {
            const int kk = kt * 8;
            uint32_t af[2][4];
            #pragma unroll
            for (int mt = 0; mt < 2; mt++) {
                int row = mp * 32 + mt * 16 + lr;
                af[mt][0] = hchunk[row * HC_STRIDE + kk + lc];
                af[mt][1] = hchunk[(row + 8) * HC_STRIDE + kk + lc];
                af[mt][2] = hchunk[row * HC_STRIDE + kk + lc + 4];
                af[mt][3] = hchunk[(row + 8) * HC_STRIDE + kk + lc + 4];
            }
            #pragma unroll
            for (int nt = 0; nt < 4; nt++) {
                int col = n_base + nt * 8 + lr;
                uint32_t bf[2];
                bf[0] = Wsm[(kk + lc) * WS_STRIDE + col];
                bf[1] = Wsm[(kk + lc + 4) * WS_STRIDE + col];
                mma_tf32(acc[0][nt], af[0], bf);
                mma_tf32(acc[1][nt], af[1], bf);
            }
        }
        #pragma unroll
        for (int mt = 0; mt < 2; mt++) {
            #pragma unroll
            for (int nt = 0; nt < 4; nt++) {
                int trow = tbase + mp * 32 + mt * 16 + lr;
                int colc = n_base + nt * 8 + 2 * lc;
                int colg = ((colc >> 6) * 128) + 64 * rank + (colc & 63);
                float bz0 = bias_sm[colc], bz1 = bias_sm[colc + 1];
                float2 v0 = make_float2(acc[mt][nt][0] + bz0, acc[mt][nt][1] + bz1);
                float2 v1 = make_float2(acc[mt][nt][2] + bz0, acc[mt][nt][3] + bz1);
                *(float2*)(g_G1 + ((size_t)trow * Bsz + b) * G4 + colg)       = v0;
                *(float2*)(g_G1 + ((size_t)(trow + 8) * Bsz + b) * G4 + colg) = v1;
            }
        }
    }
}

// ---------------- lstm0: h-split cluster recurrence + fused chunk-burst GEMV ----------------
__global__ __launch_bounds__(256, 1) __cluster_dims__(2, 1, 1)
void lstm0_kernel(const float* __restrict__ Whh,
                  const float* __restrict__ Wih1, const float* __restrict__ b1,
                  const float* __restrict__ xin) {
    __shared__ __align__(16) float h_s[2][Hd];
    __shared__ float act_s[256];
    __shared__ float xrow[Tlen];
    __shared__ __align__(8) unsigned long long mbar[2];
    extern __shared__ __align__(16) uint32_t dynsm[];
    uint32_t* Wsm    = dynsm;                        // 128 x 264 u32
    uint32_t* hchunk = Wsm + 128 * WS_STRIDE;        // 64 x 132 u32
    float*    bias_sm = (float*)(hchunk + 64 * HC_STRIDE);   // 256 f32

    const int tid  = threadIdx.x;
    const int rank = blockIdx.x & 1;
    const int b    = blockIdx.x >> 1;
    const int type = tid >> 6;
    const int hloc = tid & 63;
    const int h_idx = 64 * rank + hloc;
    const int g    = type * 128 + h_idx;
    const int kloc = 64 * rank;
    const int krem = 64 * (1 - rank);

    ulonglong2 w2[32];
    #pragma unroll
    for (int q = 0; q < 16; q++)
        w2[q] = *(const ulonglong2*)(Whh + (size_t)g * Hd + kloc + 4 * q);
    #pragma unroll
    for (int q = 0; q < 16; q++)
        w2[16 + q] = *(const ulonglong2*)(Whh + (size_t)g * Hd + krem + 4 * q);

    uint32_t mb0 = smem_u32(&mbar[0]);
    uint32_t mb1 = smem_u32(&mbar[1]);
    if (tid == 0) {
        mbar_init(mb0, 1); mbar_init(mb1, 1);
        mbar_expect_tx(mb0, 256); mbar_expect_tx(mb1, 256);
    }
    const uint32_t peer = rank ^ 1;
    const uint32_t r_h0  = mapa32(smem_u32(&h_s[0][h_idx]), peer);
    const uint32_t r_h1  = mapa32(smem_u32(&h_s[1][h_idx]), peer);
    const uint32_t r_mb0 = mapa32(mb0, peer);
    const uint32_t r_mb1 = mapa32(mb1, peer);

    const float vg = g_v0[g], ug = g_u0[g];
    for (int i = tid; i < Tlen; i += 256) xrow[i] = xin[(size_t)b * Tlen + i];
    // stage Wih1 (CTA's 256 gates) as tf32 [k][n_compact] + bias
    for (int idx = tid; idx < 256 * Hd; idx += 256) {
        int k = idx & 127, nc = idx >> 7;
        int gg = ((nc >> 6) * 128) + 64 * rank + (nc & 63);
        Wsm[k * WS_STRIDE + nc] = f2tf(Wih1[(size_t)gg * Hd + k]);
    }
    if (tid < 256) {
        int gg = ((tid >> 6) * 128) + 64 * rank + (tid & 63);
        bias_sm[tid] = b1[gg];
    }
    if (tid < Hd) h_s[0][tid] = 0.f;
    __syncthreads();
    asm volatile("barrier.cluster.arrive.aligned;" ::: "memory");
    asm volatile("barrier.cluster.wait.aligned;" ::: "memory");

    float cst = 0.f;
    uint32_t ph0 = 0, ph1 = 0;

    for (int t = 0; t < Tlen; t++) {
        const int p  = t & 1;
        const int pn = p ^ 1;

        float a_in = fmaf(xrow[t], vg, ug);

        const ulonglong2* hp = (const ulonglong2*)h_s[p];
        const ulonglong2* hL = hp + (kloc >> 2);
        const ulonglong2* hR = hp + (krem >> 2);

        unsigned long long acc0 = 0ULL, acc1 = 0ULL;
        #pragma unroll
        for (int q = 0; q < 16; q++) {
            ulonglong2 hv = hL[q];
            fma2(acc0, hv.x, w2[q].x);
            fma2(acc1, hv.y, w2[q].y);
        }
        if (t > 0) {
            if (p == 0) { mbar_wait(mb0, ph0); ph0 ^= 1; }
            else        { mbar_wait(mb1, ph1); ph1 ^= 1; }
            if (tid == 0) mbar_expect_tx(p ? mb1 : mb0, 256);
            // h(t-1) now fully in h_s[p]: stage row t-1 of the chunk (tf32)
            if (tid < Hd) hchunk[((t - 1) & 63) * HC_STRIDE + tid] = f2tf(h_s[p][tid]);
            if ((t & 63) == 0) {          // chunk [t-64, t) complete -> burst
                __syncthreads();
                burst_gemv(hchunk, Wsm, bias_sm, t - 64, b, rank, tid);
            }
        }
        #pragma unroll
        for (int q = 0; q < 16; q++) {
            ulonglong2 hv = hR[q];
            fma2(acc0, hv.x, w2[16 + q].x);
            fma2(acc1, hv.y, w2[16 + q].y);
        }
        float2 u0 = upk2(acc0), u1 = upk2(acc1);
        float A = a_in + ((u0.x + u0.y) + (u1.x + u1.y));

        float av = (type == 2) ? tanhfast(A) : sigf(A);
        act_s[tid] = av;
        __syncthreads();

        if (tid < 64) {
            float iv = act_s[tid],       fv = act_s[64 + tid];
            float gv = act_s[128 + tid], ov = act_s[192 + tid];
            cst = fmaf(fv, cst, iv * gv);
            float h = ov * tanhfast(cst);
            st_async_remote(pn ? r_h1 : r_h0, h, pn ? r_mb1 : r_mb0);
            h_s[pn][h_idx] = h;
        }
        __syncthreads();
    }

    // final chunk: wait for remote h(2047), stage row 63, burst
    mbar_wait(mb0, ph0);                  // h(2047) arrives on mb0 (pn=0 at t=2047)
    if (tid < Hd) hchunk[63 * HC_STRIDE + tid] = f2tf(h_s[0][tid]);
    __syncthreads();
    burst_gemv(hchunk, Wsm, bias_sm, Tlen - 64, b, rank, tid);

    asm volatile("barrier.cluster.arrive.aligned;" ::: "memory");
    asm volatile("barrier.cluster.wait.aligned;" ::: "memory");
}

// ---------------- lstm1 (R11, unchanged) ----------------
__global__ __launch_bounds__(256, 1) __cluster_dims__(2, 1, 1)
void lstm1_kernel(const float* __restrict__ Whh,
                  const int*   __restrict__ lengths) {
    __shared__ __align__(16) float h_s[2][Hd];
    __shared__ float act_s[256];
    __shared__ __align__(8) unsigned long long mbar[2];

    const int tid  = threadIdx.x;
    const int rank = blockIdx.x & 1;
    const int b    = blockIdx.x >> 1;
    const int type = tid >> 6;
    const int hloc = tid & 63;
    const int h_idx = 64 * rank + hloc;
    const int g    = type * 128 + h_idx;
    const int kloc = 64 * rank;
    const int krem = 64 * (1 - rank);

    ulonglong2 w2[32];
    #pragma unroll
    for (int q = 0; q < 16; q++)
        w2[q] = *(const ulonglong2*)(Whh + (size_t)g * Hd + kloc + 4 * q);
    #pragma unroll
    for (int q = 0; q < 16; q++)
        w2[16 + q] = *(const ulonglong2*)(Whh + (size_t)g * Hd + krem + 4 * q);

    uint32_t mb0 = smem_u32(&mbar[0]);
    uint32_t mb1 = smem_u32(&mbar[1]);
    if (tid == 0) {
        mbar_init(mb0, 1); mbar_init(mb1, 1);
        mbar_expect_tx(mb0, 256); mbar_expect_tx(mb1, 256);
    }
    const uint32_t peer = rank ^ 1;
    const uint32_t r_h0  = mapa32(smem_u32(&h_s[0][h_idx]), peer);
    const uint32_t r_h1  = mapa32(smem_u32(&h_s[1][h_idx]), peer);
    const uint32_t r_mb0 = mapa32(mb0, peer);
    const uint32_t r_mb1 = mapa32(mb1, peer);

    if (tid < Hd) h_s[0][tid] = 0.f;
    __syncthreads();
    asm volatile("barrier.cluster.arrive.aligned;" ::: "memory");
    asm volatile("barrier.cluster.wait.aligned;" ::: "memory");

    float cst = 0.f, sum = 0.f, mx = -INFINITY, last = 0.f;
    const int len = lengths[b];
    uint32_t ph0 = 0, ph1 = 0;

    float zn = g_G1[(size_t)b * G4 + g];

    for (int t = 0; t < Tlen; t++) {
        const int p  = t & 1;
        const int pn = p ^ 1;

        float a_in = zn;
        if (t + 1 < Tlen) zn = g_G1[((size_t)(t + 1) * Bsz + b) * G4 + g];

        const ulonglong2* hp = (const ulonglong2*)h_s[p];
        const ulonglong2* hL = hp + (kloc >> 2);
        const ulonglong2* hR = hp + (krem >> 2);

        unsigned long long acc0 = 0ULL, acc1 = 0ULL;
        #pragma unroll
        for (int q = 0; q < 16; q++) {
            ulonglong2 hv = hL[q];
            fma2(acc0, hv.x, w2[q].x);
            fma2(acc1, hv.y, w2[q].y);
        }
        if (t > 0) {
            if (p == 0) { mbar_wait(mb0, ph0); ph0 ^= 1; }
            else        { mbar_wait(mb1, ph1); ph1 ^= 1; }
            if (tid == 0) mbar_expect_tx(p ? mb1 : mb0, 256);
        }
        #pragma unroll
        for (int q = 0; q < 16; q++) {
            ulonglong2 hv = hR[q];
            fma2(acc0, hv.x, w2[16 + q].x);
            fma2(acc1, hv.y, w2[16 + q].y);
        }
        float2 u0 = upk2(acc0), u1 = upk2(acc1);
        float A = a_in + ((u0.x + u0.y) + (u1.x + u1.y));

        float av = (type == 2) ? tanhfast(A) : sigf(A);
        act_s[tid] = av;
        __syncthreads();

        if (tid < 64) {
            float iv = act_s[tid],       fv = act_s[64 + tid];
            float gv = act_s[128 + tid], ov = act_s[192 + tid];
            cst = fmaf(fv, cst, iv * gv);
            float h = ov * tanhfast(cst);
            st_async_remote(pn ? r_h1 : r_h0, h, pn ? r_mb1 : r_mb0);
            h_s[pn][h_idx] = h;
            if (t < len) { sum += h; mx = fmaxf(mx, h); }
            if (t == len - 1) last = h;
        }
        __syncthreads();
    }

    if (tid < 64) {
        g_pool[b * 384 + h_idx]            = sum / (float)len;
        g_pool[b * 384 + Hd + h_idx]       = mx;
        g_pool[b * 384 + 2 * Hd + h_idx]   = last;
    }
    asm volatile("barrier.cluster.arrive.aligned;" ::: "memory");
    asm volatile("barrier.cluster.wait.aligned;" ::: "memory");
}

// ---------------- final linear ----------------
__global__ __launch_bounds__(256)
void final_kernel(const float* __restrict__ lw, const float* __restrict__ lb,
                  float* __restrict__ out) {
    const int b = blockIdx.x;
    const int wid = threadIdx.x >> 5;
    const int lane = threadIdx.x & 31;
    if (wid >= Cout) return;
    float s = 0.f;
    const float* p = g_pool + b * 384;
    const float* wv = lw + wid * 384;
    #pragma unroll
    for (int j = lane; j < 384; j += 32) s = fmaf(p[j], wv[j], s);
    #pragma unroll
    for (int o = 16; o > 0; o >>= 1) s += __shfl_xor_sync(0xffffffff, s, o);
    if (lane == 0) out[b * Cout + wid] = s + lb[wid];
}

// ---------------- launch ----------------
extern "C" void kernel_launch(void* const* d_in, const int* in_sizes, int n_in,
                              void* d_out, int out_size) {
    const float* x    = (const float*)d_in[0];
    const int*   lens = (const int*)  d_in[1];
    const float* ffw  = (const float*)d_in[2];
    const float* ffb  = (const float*)d_in[3];
    const float* Wih0 = (const float*)d_in[4];
    const float* Whh0 = (const float*)d_in[5];
    const float* b0   = (const float*)d_in[6];
    const float* Wih1 = (const float*)d_in[7];
    const float* Whh1 = (const float*)d_in[8];
    const float* b1   = (const float*)d_in[9];
    const float* lw   = (const float*)d_in[10];
    const float* lb   = (const float*)d_in[11];
    float* out = (float*)d_out;

    const int DYN0 = (128 * WS_STRIDE + 64 * HC_STRIDE + 256) * 4;   // ~166 KB
    cudaFuncSetAttribute(lstm0_kernel, cudaFuncAttributeMaxDynamicSharedMemorySize, DYN0);

    prep_kernel<<<8, 64>>>(Wih0, ffw, ffb, b0);
    lstm0_kernel<<<2 * Bsz, 256, DYN0>>>(Whh0, Wih1, b1, x);
    lstm1_kernel<<<2 * Bsz, 256>>>(Whh1, lens);
    final_kernel<<<Bsz, 256>>>(lw, lb, out);
}